// round 1
// baseline (speedup 1.0000x reference)
#include <cuda_runtime.h>

#define NPTS 16384
#define KNN  16
#define CIMG 54
#define NC1  58            // nb(3) + dist(1) + img(54)
#define THREADS 256
#define WARPS 8
#define UPB 32             // (b,n) units per block
#define NBLOCKS ((4 * NPTS) / UPB)   // 2048

// ---------------- folded-weight scratch (device global; no allocs) ----------
struct Prep {
    float2 wdup[NC1 * 32];   // [c][o] conv1 weight, BN-folded, duplicated (w,w)
    float2 w2c[32 * 32];     // [i][o2] = (w2_max, w2_mean/16), BN-folded
    float4 wep4[32];         // per o: (wep0, wep1, wep2, bias1_folded)
    float4 w2e4[32];         // per o2: (w2ep0, w2ep1, w2ep2, bias2_folded)
};
__device__ Prep g_prep;

// ---------------- packed fp32x2 FMA (Blackwell-only, 2x fp32 rate) ----------
union F2U { float2 f; unsigned long long u; };
__device__ __forceinline__ float2 ffma2(float2 a, float2 b, float2 c) {
    F2U A, B, C, D;
    A.f = a; B.f = b; C.f = c;
    asm("fma.rn.f32x2 %0, %1, %2, %3;" : "=l"(D.u) : "l"(A.u), "l"(B.u), "l"(C.u));
    return D.f;
}

// ---------------- prep: fold BN + concat algebra into weights --------------
__global__ void prep_kernel(
    const float* __restrict__ w1, const float* __restrict__ b1,
    const float* __restrict__ g1, const float* __restrict__ be1,
    const float* __restrict__ m1, const float* __restrict__ v1,
    const float* __restrict__ w2, const float* __restrict__ b2,
    const float* __restrict__ g2, const float* __restrict__ be2,
    const float* __restrict__ m2, const float* __restrict__ v2)
{
    __shared__ float s1[32], s2[32], bf1[32], bf2[32];
    int t = threadIdx.x;
    if (t < 32) {
        float sc = g1[t] / sqrtf(v1[t] + 1e-6f);
        s1[t]  = sc;
        bf1[t] = (b1[t] - m1[t]) * sc + be1[t];
        float sc2 = g2[t] / sqrtf(v2[t] + 1e-6f);
        s2[t]  = sc2;
        bf2[t] = (b2[t] - m2[t]) * sc2 + be2[t];
    }
    __syncthreads();

    // conv1 channels (BN folded):  x = [nb0,nb1,nb2, dist, img0..53]
    //   nb coeff  = (w1[:,3+c] - w1[:,6+c]) * s1     (from nb and ep-nb terms)
    //   dist      =  w1[:,9] * s1
    //   img       =  w1[:,10+c] * s1
    for (int i = t; i < NC1 * 32; i += blockDim.x) {
        int c = i >> 5, o = i & 31;
        float wv;
        if (c < 3)        wv = w1[o * 64 + 3 + c] - w1[o * 64 + 6 + c];
        else if (c == 3)  wv = w1[o * 64 + 9];
        else              wv = w1[o * 64 + 10 + (c - 4)];
        wv *= s1[o];
        g_prep.wdup[i] = make_float2(wv, wv);
    }
    // conv2: channels 0..31 = max(h), 32..34 = ep, 35..66 = mean(h), 67..69 = ep
    for (int i = t; i < 32 * 32; i += blockDim.x) {
        int c = i >> 5, o = i & 31;
        float wm = w2[o * 70 + c] * s2[o];
        float ws = w2[o * 70 + 35 + c] * s2[o] * 0.0625f;   // fold 1/K into mean
        g_prep.w2c[i] = make_float2(wm, ws);
    }
    if (t < 32) {
        int o = t;
        g_prep.wep4[o] = make_float4(
            (w1[o * 64 + 0] + w1[o * 64 + 6]) * s1[o],
            (w1[o * 64 + 1] + w1[o * 64 + 7]) * s1[o],
            (w1[o * 64 + 2] + w1[o * 64 + 8]) * s1[o],
            bf1[o]);
        g_prep.w2e4[o] = make_float4(
            (w2[o * 70 + 32] + w2[o * 70 + 67]) * s2[o],
            (w2[o * 70 + 33] + w2[o * 70 + 68]) * s2[o],
            (w2[o * 70 + 34] + w2[o * 70 + 69]) * s2[o],
            bf2[o]);
    }
}

// ---------------- main fused kernel ----------------------------------------
__global__ __launch_bounds__(THREADS) void pif_main(
    const float* __restrict__ points, const float* __restrict__ img,
    const float* __restrict__ dist,   const int*   __restrict__ idx,
    float* __restrict__ out)
{
    __shared__ __align__(16) float2 s_wdup[NC1 * 32];
    __shared__ float2 s_w2c[32 * 32];
    __shared__ float2 s_pool[WARPS][32];
    __shared__ float  s_out[WARPS][33];

    const int t    = threadIdx.x;
    const int lane = t & 31, wrp = t >> 5;
    const int og   = lane >> 3, kp = lane & 7;   // og: out-chan group, kp: k-pair

    for (int i = t; i < NC1 * 32; i += THREADS) s_wdup[i] = g_prep.wdup[i];
    for (int i = t; i < 32 * 32; i += THREADS)  s_w2c[i]  = g_prep.w2c[i];

    float4 wep[8];
#pragma unroll
    for (int r = 0; r < 8; r++) wep[r] = g_prep.wep4[og * 8 + r];
    const float4 w2e = g_prep.w2e4[lane];
    __syncthreads();

    const int unit0 = blockIdx.x * UPB;
    const int b = unit0 >> 14;                   // 512 blocks per batch, aligned
    const float* pts_b = points + b * (NPTS * 3);
    const float* img_b = img  + (size_t)b * (CIMG * NPTS * KNN);
    const float* dst_b = dist + b * (NPTS * KNN);
    const int*   idx_b = idx  + b * (NPTS * KNN);
    float*       out_b = out  + b * (32 * NPTS);

    for (int it = 0; it < UPB / WARPS; ++it) {
        const int n0 = (unit0 & (NPTS - 1)) + it * WARPS;
        const int n  = n0 + wrp;

        // ep (warp-uniform broadcast load)
        const float ep0 = pts_b[n * 3 + 0];
        const float ep1 = pts_b[n * 3 + 1];
        const float ep2 = pts_b[n * 3 + 2];

        // per-thread k-pair gather
        const int k0 = kp * 2;
        const int j0 = idx_b[n * KNN + k0];
        const int j1 = idx_b[n * KNN + k0 + 1];
        const float2 xnb0 = make_float2(pts_b[j0 * 3 + 0], pts_b[j1 * 3 + 0]);
        const float2 xnb1 = make_float2(pts_b[j0 * 3 + 1], pts_b[j1 * 3 + 1]);
        const float2 xnb2 = make_float2(pts_b[j0 * 3 + 2], pts_b[j1 * 3 + 2]);
        const float2 xd   = *reinterpret_cast<const float2*>(dst_b + n * KNN + k0);

        // init accumulators with ep-term + folded bias (constant over k)
        float2 acc[8];
#pragma unroll
        for (int r = 0; r < 8; r++) {
            float e = fmaf(wep[r].x, ep0, fmaf(wep[r].y, ep1, fmaf(wep[r].z, ep2, wep[r].w)));
            acc[r] = make_float2(e, e);
        }

#define DO_CH(CIDX, XV)                                                          \
        {                                                                        \
            const float4* wr = reinterpret_cast<const float4*>(s_wdup + (CIDX) * 32 + og * 8); \
            float4 wa = wr[0], wb = wr[1], wc = wr[2], wd = wr[3];               \
            acc[0] = ffma2(make_float2(wa.x, wa.y), (XV), acc[0]);               \
            acc[1] = ffma2(make_float2(wa.z, wa.w), (XV), acc[1]);               \
            acc[2] = ffma2(make_float2(wb.x, wb.y), (XV), acc[2]);               \
            acc[3] = ffma2(make_float2(wb.z, wb.w), (XV), acc[3]);               \
            acc[4] = ffma2(make_float2(wc.x, wc.y), (XV), acc[4]);               \
            acc[5] = ffma2(make_float2(wc.z, wc.w), (XV), acc[5]);               \
            acc[6] = ffma2(make_float2(wd.x, wd.y), (XV), acc[6]);               \
            acc[7] = ffma2(make_float2(wd.z, wd.w), (XV), acc[7]);               \
        }

        DO_CH(0, xnb0)
        DO_CH(1, xnb1)
        DO_CH(2, xnb2)
        DO_CH(3, xd)

        // 54 image channels: contiguous 64B per channel per warp, L1-dedup'd
        const float* ib = img_b + n * KNN + k0;
#pragma unroll 6
        for (int c = 0; c < CIMG; c++) {
            float2 x = *reinterpret_cast<const float2*>(ib + c * (NPTS * KNN));
            DO_CH(4 + c, x)
        }
#undef DO_CH

        // ReLU + local (2-wide) pool, then butterfly over kp lanes
        float2 pool[8];
#pragma unroll
        for (int r = 0; r < 8; r++) {
            float a = fmaxf(acc[r].x, 0.0f), bq = fmaxf(acc[r].y, 0.0f);
            pool[r] = make_float2(fmaxf(a, bq), a + bq);
        }
#pragma unroll
        for (int m = 1; m < 8; m <<= 1) {
#pragma unroll
            for (int r = 0; r < 8; r++) {
                pool[r].x = fmaxf(pool[r].x, __shfl_xor_sync(0xffffffffu, pool[r].x, m));
                pool[r].y +=                 __shfl_xor_sync(0xffffffffu, pool[r].y, m);
            }
        }
        // lane (og*8 + r) with kp==r publishes pooled value for channel og*8+r
#pragma unroll
        for (int r = 0; r < 8; r++)
            if (kp == r) s_pool[wrp][og * 8 + r] = pool[r];
        __syncwarp();

        // conv2: lane = output channel o2
        float acc2 = fmaf(w2e.x, ep0, fmaf(w2e.y, ep1, fmaf(w2e.z, ep2, w2e.w)));
#pragma unroll 8
        for (int i = 0; i < 32; i++) {
            float2 wv = s_w2c[i * 32 + lane];
            float2 hv = s_pool[wrp][i];
            acc2 = fmaf(wv.x, hv.x, fmaf(wv.y, hv.y, acc2));
        }
        s_out[wrp][lane] = fmaxf(acc2, 0.0f);
        __syncthreads();

        // coalesced store: 8 consecutive n per output channel (full 32B sectors)
        out_b[(t >> 3) * NPTS + n0 + (t & 7)] = s_out[t & 7][t >> 3];
        __syncthreads();
    }
}

// ---------------- launch ----------------------------------------------------
extern "C" void kernel_launch(void* const* d_in, const int* in_sizes, int n_in,
                              void* d_out, int out_size)
{
    const float* points = (const float*)d_in[0];
    const float* img    = (const float*)d_in[1];
    const float* dist   = (const float*)d_in[2];
    const int*   idx    = (const int*)  d_in[3];

    prep_kernel<<<1, 256>>>(
        (const float*)d_in[4],  (const float*)d_in[5],
        (const float*)d_in[6],  (const float*)d_in[7],
        (const float*)d_in[8],  (const float*)d_in[9],
        (const float*)d_in[10], (const float*)d_in[11],
        (const float*)d_in[12], (const float*)d_in[13],
        (const float*)d_in[14], (const float*)d_in[15]);

    pif_main<<<NBLOCKS, THREADS>>>(points, img, dist, idx, (float*)d_out);
}

// round 4
// speedup vs baseline: 1.8736x; 1.8736x over previous
#include <cuda_runtime.h>

#define NPTS 16384
#define KNN  16
#define CIMG 54
#define CSTRIDE (NPTS * KNN)        // img channel stride (262144 floats)
#define THREADS 256
#define WARPS 8
#define NB 32                        // n-units per block
#define NBLOCKS ((4 * NPTS) / NB)    // 2048

// ---------------- folded-weight scratch (device global; no allocs) ----------
struct Prep {
    float2 wdup[58 * 32];    // [c][o] conv1 weight, BN-folded, duplicated (w,w)
    float2 w2c[32 * 32];     // [i][o2] = (w2_max, w2_mean/16), BN-folded
    float4 wep4[32];         // per o: (wep0, wep1, wep2, bias1_folded)
    float4 w2e4[32];         // per o2: (w2ep0, w2ep1, w2ep2, bias2_folded)
};
__device__ Prep g_prep;

// ---------------- packed fp32x2 FMA ----------------------------------------
union F2U { float2 f; unsigned long long u; };
__device__ __forceinline__ float2 ffma2(float2 a, float2 b, float2 c) {
    F2U A, B, C, D;
    A.f = a; B.f = b; C.f = c;
    asm("fma.rn.f32x2 %0, %1, %2, %3;" : "=l"(D.u) : "l"(A.u), "l"(B.u), "l"(C.u));
    return D.f;
}

// ---------------- prep: fold BN + concat algebra into weights --------------
__global__ void prep_kernel(
    const float* __restrict__ w1, const float* __restrict__ b1,
    const float* __restrict__ g1, const float* __restrict__ be1,
    const float* __restrict__ m1, const float* __restrict__ v1,
    const float* __restrict__ w2, const float* __restrict__ b2,
    const float* __restrict__ g2, const float* __restrict__ be2,
    const float* __restrict__ m2, const float* __restrict__ v2)
{
    __shared__ float s1[32], s2[32], bf1[32], bf2[32];
    int t = threadIdx.x;
    if (t < 32) {
        float sc = g1[t] / sqrtf(v1[t] + 1e-6f);
        s1[t]  = sc;
        bf1[t] = (b1[t] - m1[t]) * sc + be1[t];
        float sc2 = g2[t] / sqrtf(v2[t] + 1e-6f);
        s2[t]  = sc2;
        bf2[t] = (b2[t] - m2[t]) * sc2 + be2[t];
    }
    __syncthreads();

    for (int i = t; i < 58 * 32; i += blockDim.x) {
        int c = i >> 5, o = i & 31;
        float wv;
        if (c < 3)        wv = w1[o * 64 + 3 + c] - w1[o * 64 + 6 + c];
        else if (c == 3)  wv = w1[o * 64 + 9];
        else              wv = w1[o * 64 + 10 + (c - 4)];
        wv *= s1[o];
        g_prep.wdup[i] = make_float2(wv, wv);
    }
    for (int i = t; i < 32 * 32; i += blockDim.x) {
        int c = i >> 5, o = i & 31;
        float wm = w2[o * 70 + c] * s2[o];
        float ws = w2[o * 70 + 35 + c] * s2[o] * 0.0625f;
        g_prep.w2c[i] = make_float2(wm, ws);
    }
    if (t < 32) {
        int o = t;
        g_prep.wep4[o] = make_float4(
            (w1[o * 64 + 0] + w1[o * 64 + 6]) * s1[o],
            (w1[o * 64 + 1] + w1[o * 64 + 7]) * s1[o],
            (w1[o * 64 + 2] + w1[o * 64 + 8]) * s1[o],
            bf1[o]);
        g_prep.w2e4[o] = make_float4(
            (w2[o * 70 + 32] + w2[o * 70 + 67]) * s2[o],
            (w2[o * 70 + 33] + w2[o * 70 + 68]) * s2[o],
            (w2[o * 70 + 34] + w2[o * 70 + 69]) * s2[o],
            bf2[o]);
    }
}

// ---------------- per-n gather set (software-pipelined one ahead) ----------
struct Gset {
    float  ep0, ep1, ep2;
    float2 nb0, nb1, nb2, xd;
};

// ---------------- dynamic smem layout (floats) ------------------------------
// [0, 13824)        img: [WARPS][2 buf][54][16]
// [13824, 17536)    wdup (3712 floats, contiguous with w2c for bulk copy)
// [17536, 19584)    w2c  (2048 floats)
// [19584, 20096)    pool: [WARPS][32] float2
// [20096, 21152)    out:  [32][33]
#define SMEM_FLOATS 21152
#define SMEM_BYTES  (SMEM_FLOATS * 4)

__global__ __launch_bounds__(THREADS, 2) void pif_main(
    const float* __restrict__ points, const float* __restrict__ img,
    const float* __restrict__ dist,   const int*   __restrict__ idx,
    float* __restrict__ out)
{
    extern __shared__ float smem[];
    float*  s_img  = smem;
    float2* s_wdup = (float2*)(smem + 13824);
    float2* s_w2c  = (float2*)(smem + 17536);
    float2* s_pool = (float2*)(smem + 19584);
    float*  s_out  = smem + 20096;

    const int t    = threadIdx.x;
    const int lane = t & 31, wrp = t >> 5;
    const int og   = lane >> 3, kp = lane & 7;

    // bulk-copy folded weights (wdup + w2c contiguous in Prep)
    {
        const float4* src = (const float4*)&g_prep;
        float4* dst = (float4*)(smem + 13824);
        for (int i = t; i < 1440; i += THREADS) dst[i] = src[i];
    }
    float4 wep[8];
#pragma unroll
    for (int r = 0; r < 8; r++) wep[r] = g_prep.wep4[og * 8 + r];
    const float4 w2e = g_prep.w2e4[lane];

    const int b  = blockIdx.x >> 9;               // 512 blocks per batch
    const int n0 = (blockIdx.x & 511) * NB;
    const float* pts_b = points + b * (NPTS * 3);
    const float* img_b = img  + (size_t)b * (CIMG * (size_t)CSTRIDE);
    const float* dst_b = dist + b * (NPTS * KNN);
    const int*   idx_b = idx  + b * (NPTS * KNN);
    float*       out_b = out  + b * (32 * NPTS);

    float* my_img = s_img + wrp * (2 * CIMG * KNN);

    // ---- prefetch helper: 54 channels x 64B for unit n into buf -----------
    auto prefetch = [&](int n, int bufsel) {
        float* dstb = my_img + bufsel * (CIMG * KNN);
        const float* srcb = img_b + (size_t)n * KNN;
        int q = lane;
#pragma unroll
        for (int w = 0; w < 7; w++) {
            if (q < CIMG * 4) {
                int c = q >> 2, j = q & 3;
                unsigned dsta = (unsigned)__cvta_generic_to_shared(dstb + c * KNN + j * 4);
                const float* s = srcb + (size_t)c * CSTRIDE + j * 4;
                asm volatile("cp.async.cg.shared.global [%0], [%1], 16;"
                             :: "r"(dsta), "l"(s));
            }
            q += 32;
        }
        asm volatile("cp.async.commit_group;");
    };

    auto load_g = [&](int n, Gset& g) {
        g.ep0 = pts_b[n * 3 + 0];
        g.ep1 = pts_b[n * 3 + 1];
        g.ep2 = pts_b[n * 3 + 2];
        const int k0 = kp * 2;
        const int j0 = idx_b[n * KNN + k0];
        const int j1 = idx_b[n * KNN + k0 + 1];
        g.nb0 = make_float2(pts_b[j0 * 3 + 0], pts_b[j1 * 3 + 0]);
        g.nb1 = make_float2(pts_b[j0 * 3 + 1], pts_b[j1 * 3 + 1]);
        g.nb2 = make_float2(pts_b[j0 * 3 + 2], pts_b[j1 * 3 + 2]);
        g.xd  = *reinterpret_cast<const float2*>(dst_b + n * KNN + k0);
    };

    const int nw = n0 + wrp * 4;                 // this warp's 4 n-units
    Gset gc, gn;
    load_g(nw, gc);
    prefetch(nw, 0);
    __syncthreads();                              // weights visible to all

#pragma unroll
    for (int it = 0; it < 4; ++it) {
        const int buf = it & 1;
        if (it < 3) {
            prefetch(nw + it + 1, buf ^ 1);
            load_g(nw + it + 1, gn);
        }
        if (it < 3) asm volatile("cp.async.wait_group 1;");
        else        asm volatile("cp.async.wait_group 0;");
        __syncwarp();

        // accumulator init: ep-term + folded bias (constant over k)
        float2 acc[8];
#pragma unroll
        for (int r = 0; r < 8; r++) {
            float e = fmaf(wep[r].x, gc.ep0,
                      fmaf(wep[r].y, gc.ep1,
                      fmaf(wep[r].z, gc.ep2, wep[r].w)));
            acc[r] = make_float2(e, e);
        }

#define DO_CH(CIDX, XV)                                                          \
        {                                                                        \
            const float4* wr = reinterpret_cast<const float4*>(s_wdup + (CIDX) * 32 + og * 8); \
            float4 wa = wr[0], wb = wr[1], wc = wr[2], wd = wr[3];               \
            acc[0] = ffma2(make_float2(wa.x, wa.y), (XV), acc[0]);               \
            acc[1] = ffma2(make_float2(wa.z, wa.w), (XV), acc[1]);               \
            acc[2] = ffma2(make_float2(wb.x, wb.y), (XV), acc[2]);               \
            acc[3] = ffma2(make_float2(wb.z, wb.w), (XV), acc[3]);               \
            acc[4] = ffma2(make_float2(wc.x, wc.y), (XV), acc[4]);               \
            acc[5] = ffma2(make_float2(wc.z, wc.w), (XV), acc[5]);               \
            acc[6] = ffma2(make_float2(wd.x, wd.y), (XV), acc[6]);               \
            acc[7] = ffma2(make_float2(wd.z, wd.w), (XV), acc[7]);               \
        }

        DO_CH(0, gc.nb0)
        DO_CH(1, gc.nb1)
        DO_CH(2, gc.nb2)
        DO_CH(3, gc.xd)

        // 54 image channels from SMEM (staged via cp.async)
        const float* xb = my_img + buf * (CIMG * KNN) + kp * 2;
#pragma unroll 6
        for (int c = 0; c < CIMG; c++) {
            float2 x = *reinterpret_cast<const float2*>(xb + c * KNN);
            DO_CH(4 + c, x)
        }
#undef DO_CH

        // ReLU + 2-wide local pool, then 3-round butterfly across kp lanes
        float2 pool[8];
#pragma unroll
        for (int r = 0; r < 8; r++) {
            float a = fmaxf(acc[r].x, 0.0f), bq = fmaxf(acc[r].y, 0.0f);
            pool[r] = make_float2(fmaxf(a, bq), a + bq);
        }
#pragma unroll
        for (int m = 1; m < 8; m <<= 1) {
#pragma unroll
            for (int r = 0; r < 8; r++) {
                pool[r].x = fmaxf(pool[r].x, __shfl_xor_sync(0xffffffffu, pool[r].x, m));
                pool[r].y +=                 __shfl_xor_sync(0xffffffffu, pool[r].y, m);
            }
        }
#pragma unroll
        for (int r = 0; r < 8; r++)
            if (kp == r) s_pool[wrp * 32 + og * 8 + r] = pool[r];
        __syncwarp();

        // conv2 packed as FFMA2: (w_max, w_mean/16) . (h_max, h_sum)
        float e2 = fmaf(w2e.x, gc.ep0,
                   fmaf(w2e.y, gc.ep1,
                   fmaf(w2e.z, gc.ep2, w2e.w)));
        float2 acc2 = make_float2(e2, 0.0f);
#pragma unroll 8
        for (int i = 0; i < 32; i++)
            acc2 = ffma2(s_w2c[i * 32 + lane], s_pool[wrp * 32 + i], acc2);
        s_out[lane * 33 + wrp * 4 + it] = fmaxf(acc2.x + acc2.y, 0.0f);

        gc = gn;
    }

    // one block-wide sync, then fully coalesced float4 stores
    __syncthreads();
    {
        int o = t >> 3, c4 = (t & 7) * 4;
        float4 v = make_float4(s_out[o * 33 + c4],     s_out[o * 33 + c4 + 1],
                               s_out[o * 33 + c4 + 2], s_out[o * 33 + c4 + 3]);
        *reinterpret_cast<float4*>(out_b + o * NPTS + n0 + c4) = v;
    }
}

// ---------------- launch ----------------------------------------------------
extern "C" void kernel_launch(void* const* d_in, const int* in_sizes, int n_in,
                              void* d_out, int out_size)
{
    const float* points = (const float*)d_in[0];
    const float* img    = (const float*)d_in[1];
    const float* dist   = (const float*)d_in[2];
    const int*   idx    = (const int*)  d_in[3];

    prep_kernel<<<1, 256>>>(
        (const float*)d_in[4],  (const float*)d_in[5],
        (const float*)d_in[6],  (const float*)d_in[7],
        (const float*)d_in[8],  (const float*)d_in[9],
        (const float*)d_in[10], (const float*)d_in[11],
        (const float*)d_in[12], (const float*)d_in[13],
        (const float*)d_in[14], (const float*)d_in[15]);

    cudaFuncSetAttribute(pif_main, cudaFuncAttributeMaxDynamicSharedMemorySize,
                         SMEM_BYTES);
    pif_main<<<NBLOCKS, THREADS, SMEM_BYTES>>>(points, img, dist, idx,
                                               (float*)d_out);
}

// round 5
// speedup vs baseline: 2.2382x; 1.1946x over previous
#include <cuda_runtime.h>

#define NPTS 16384
#define KNN  16
#define CIMG 54
#define NCH  58                      // 54 img + dist + nb0..2
#define CSTRIDE (NPTS * KNN)
#define THREADS 256
#define WARPS 8
#define NB 32
#define NBLOCKS ((4 * NPTS) / NB)    // 2048

// ---------------- folded-weight scratch (device global; no allocs) ----------
struct Prep {
    float  ws[NCH * 32];     // [row c][o]: conv1 weight, BN-folded, row order =
                             //   0..53 img, 54 dist, 55..57 nb
    float2 w2c[32 * 32];     // [i][o2] = (w2_max, w2_mean/16), BN-folded
    float4 wep4[32];         // per o: (wep0, wep1, wep2, bias1_folded)
    float4 w2e4[32];         // per o2: (w2ep0, w2ep1, w2ep2, bias2_folded)
};
__device__ Prep g_prep;

// ---------------- packed fp32x2 helpers -------------------------------------
union F2U { float2 f; unsigned long long u; };
__device__ __forceinline__ float2 ffma2(float2 a, float2 b, float2 c) {
    F2U A, B, C, D;
    A.f = a; B.f = b; C.f = c;
    asm("fma.rn.f32x2 %0, %1, %2, %3;" : "=l"(D.u) : "l"(A.u), "l"(B.u), "l"(C.u));
    return D.f;
}
__device__ __forceinline__ float2 dup2(float w) {
    F2U D;
    asm("mov.b64 %0, {%1, %1};" : "=l"(D.u) : "f"(w));
    return D.f;
}

// ---------------- prep: fold BN + concat algebra into weights ---------------
__global__ void prep_kernel(
    const float* __restrict__ w1, const float* __restrict__ b1,
    const float* __restrict__ g1, const float* __restrict__ be1,
    const float* __restrict__ m1, const float* __restrict__ v1,
    const float* __restrict__ w2, const float* __restrict__ b2,
    const float* __restrict__ g2, const float* __restrict__ be2,
    const float* __restrict__ m2, const float* __restrict__ v2)
{
    __shared__ float s1[32], s2[32], bf1[32], bf2[32];
    int t = threadIdx.x;
    if (t < 32) {
        float sc = g1[t] / sqrtf(v1[t] + 1e-6f);
        s1[t]  = sc;
        bf1[t] = (b1[t] - m1[t]) * sc + be1[t];
        float sc2 = g2[t] / sqrtf(v2[t] + 1e-6f);
        s2[t]  = sc2;
        bf2[t] = (b2[t] - m2[t]) * sc2 + be2[t];
    }
    __syncthreads();

    // conv1 rows: 0..53 img (w1 col 10+c), 54 dist (col 9), 55..57 nb (col 3+c - col 6+c)
    for (int i = t; i < NCH * 32; i += blockDim.x) {
        int c = i >> 5, o = i & 31;
        float wv;
        if (c < 54)       wv = w1[o * 64 + 10 + c];
        else if (c == 54) wv = w1[o * 64 + 9];
        else              wv = w1[o * 64 + 3 + (c - 55)] - w1[o * 64 + 6 + (c - 55)];
        g_prep.ws[i] = wv * s1[o];
    }
    for (int i = t; i < 32 * 32; i += blockDim.x) {
        int c = i >> 5, o = i & 31;
        float wm = w2[o * 70 + c] * s2[o];
        float wsn = w2[o * 70 + 35 + c] * s2[o] * 0.0625f;
        g_prep.w2c[i] = make_float2(wm, wsn);
    }
    if (t < 32) {
        int o = t;
        g_prep.wep4[o] = make_float4(
            (w1[o * 64 + 0] + w1[o * 64 + 6]) * s1[o],
            (w1[o * 64 + 1] + w1[o * 64 + 7]) * s1[o],
            (w1[o * 64 + 2] + w1[o * 64 + 8]) * s1[o],
            bf1[o]);
        g_prep.w2e4[o] = make_float4(
            (w2[o * 70 + 32] + w2[o * 70 + 67]) * s2[o],
            (w2[o * 70 + 33] + w2[o * 70 + 68]) * s2[o],
            (w2[o * 70 + 34] + w2[o * 70 + 69]) * s2[o],
            bf2[o]);
    }
}

// ---------------- dynamic smem layout (floats) ------------------------------
// [0, 14848)        x-stage: [WARPS][2 buf][58 rows][16]
// [14848, 16896)    w2c (2048 floats)
// [16896, 17408)    pool: [WARPS][32] float2
// [17408, 18464)    out:  [32][33]
#define XSTRIDE (NCH * KNN)          // 928 floats per buffer
#define SMEM_FLOATS 18464
#define SMEM_BYTES  (SMEM_FLOATS * 4)

struct Ep { float e0, e1, e2; };

__global__ __launch_bounds__(THREADS, 2) void pif_main(
    const float* __restrict__ points, const float* __restrict__ img,
    const float* __restrict__ dist,   const int*   __restrict__ idx,
    float* __restrict__ out)
{
    extern __shared__ float smem[];
    float*  s_x    = smem;
    float2* s_w2c  = (float2*)(smem + 14848);
    float2* s_pool = (float2*)(smem + 16896);
    float*  s_out  = smem + 17408;

    const int t    = threadIdx.x;
    const int lane = t & 31, wrp = t >> 5;

    // copy w2c to smem (bulk float4)
    {
        const float4* src = (const float4*)g_prep.w2c;
        float4* dst = (float4*)(smem + 14848);
        for (int i = t; i < 512; i += THREADS) dst[i] = src[i];
    }
    // conv1 weights -> registers (lane = out channel o); full unroll keeps in regs
    float wreg[NCH];
#pragma unroll
    for (int c = 0; c < NCH; c++) wreg[c] = g_prep.ws[c * 32 + lane];
    const float4 wep = g_prep.wep4[lane];
    const float4 w2e = g_prep.w2e4[lane];

    const int b  = blockIdx.x >> 9;
    const int n0 = (blockIdx.x & 511) * NB;
    const float* pts_b = points + b * (NPTS * 3);
    const float* img_b = img  + (size_t)b * (CIMG * (size_t)CSTRIDE);
    const float* dst_b = dist + b * (NPTS * KNN);
    const int*   idx_b = idx  + b * (NPTS * KNN);
    float*       out_b = out  + b * (32 * NPTS);

    float* my_x = s_x + wrp * (2 * XSTRIDE);

    // ---- cp.async prefetch: 55 rows (54 img + dist) x 64B ------------------
    auto prefetch = [&](int n, int bufsel) {
        float* db = my_x + bufsel * XSTRIDE;
        int q = lane;
#pragma unroll
        for (int w = 0; w < 7; w++) {
            if (q < 55 * 4) {
                int c = q >> 2, j = q & 3;
                const float* s = (c < CIMG)
                    ? img_b + (size_t)c * CSTRIDE + n * KNN + j * 4
                    : dst_b + n * KNN + j * 4;
                unsigned da = (unsigned)__cvta_generic_to_shared(db + c * KNN + j * 4);
                asm volatile("cp.async.cg.shared.global [%0], [%1], 16;"
                             :: "r"(da), "l"(s));
            }
            q += 32;
        }
        asm volatile("cp.async.commit_group;");
    };

    // ---- nb gather: lanes 0..15 fetch neighbor xyz, STS rows 55..57 --------
    auto gather_nb = [&](int n, int bufsel) {
        if (lane < 16) {
            int j = idx_b[n * KNN + lane];
            float p0 = pts_b[j * 3 + 0];
            float p1 = pts_b[j * 3 + 1];
            float p2 = pts_b[j * 3 + 2];
            float* r = my_x + bufsel * XSTRIDE + 55 * KNN + lane;
            r[0]  = p0;
            r[16] = p1;
            r[32] = p2;
        }
    };
    auto load_ep = [&](int n, Ep& e) {
        e.e0 = pts_b[n * 3 + 0];
        e.e1 = pts_b[n * 3 + 1];
        e.e2 = pts_b[n * 3 + 2];
    };

    const int nw = n0 + wrp * 4;
    Ep epc, epn;
    prefetch(nw, 0);
    gather_nb(nw, 0);
    load_ep(nw, epc);
    __syncthreads();                 // w2c visible

#pragma unroll
    for (int it = 0; it < 4; ++it) {
        const int buf = it & 1;
        if (it < 3) {
            prefetch(nw + it + 1, buf ^ 1);
            gather_nb(nw + it + 1, buf ^ 1);
            load_ep(nw + it + 1, epn);
        }
        if (it < 3) asm volatile("cp.async.wait_group 1;");
        else        asm volatile("cp.async.wait_group 0;");
        __syncwarp();

        // acc[r] covers k=2r,2r+1 for this lane's out-channel; ep-term init
        const float e = fmaf(wep.x, epc.e0,
                        fmaf(wep.y, epc.e1,
                        fmaf(wep.z, epc.e2, wep.w)));
        float2 acc[8];
#pragma unroll
        for (int r = 0; r < 8; r++) acc[r] = make_float2(e, e);

        const float* xr = my_x + buf * XSTRIDE;
#pragma unroll
        for (int c = 0; c < NCH; c++) {
            const float2 wd = dup2(wreg[c]);
            const float4* xp = reinterpret_cast<const float4*>(xr + c * KNN);
            float4 x0 = xp[0], x1 = xp[1], x2 = xp[2], x3 = xp[3];
            acc[0] = ffma2(wd, make_float2(x0.x, x0.y), acc[0]);
            acc[1] = ffma2(wd, make_float2(x0.z, x0.w), acc[1]);
            acc[2] = ffma2(wd, make_float2(x1.x, x1.y), acc[2]);
            acc[3] = ffma2(wd, make_float2(x1.z, x1.w), acc[3]);
            acc[4] = ffma2(wd, make_float2(x2.x, x2.y), acc[4]);
            acc[5] = ffma2(wd, make_float2(x2.z, x2.w), acc[5]);
            acc[6] = ffma2(wd, make_float2(x3.x, x3.y), acc[6]);
            acc[7] = ffma2(wd, make_float2(x3.z, x3.w), acc[7]);
        }

        // ReLU + in-register pool over 16 k values
        float2 mx = make_float2(fmaxf(acc[0].x, 0.f), fmaxf(acc[0].y, 0.f));
        float2 sm = mx;
#pragma unroll
        for (int r = 1; r < 8; r++) {
            float ax = fmaxf(acc[r].x, 0.f), ay = fmaxf(acc[r].y, 0.f);
            mx.x = fmaxf(mx.x, ax); mx.y = fmaxf(mx.y, ay);
            sm.x += ax;             sm.y += ay;
        }
        s_pool[wrp * 32 + lane] = make_float2(fmaxf(mx.x, mx.y), sm.x + sm.y);
        __syncwarp();

        // conv2 packed FFMA2: (w_max, w_mean/16) . (h_max, h_sum)
        float e2 = fmaf(w2e.x, epc.e0,
                   fmaf(w2e.y, epc.e1,
                   fmaf(w2e.z, epc.e2, w2e.w)));
        float2 acc2 = make_float2(e2, 0.0f);
#pragma unroll 8
        for (int i = 0; i < 32; i++)
            acc2 = ffma2(s_w2c[i * 32 + lane], s_pool[wrp * 32 + i], acc2);
        s_out[lane * 33 + wrp * 4 + it] = fmaxf(acc2.x + acc2.y, 0.0f);

        epc = epn;
    }

    // block-wide sync, then fully coalesced float4 stores
    __syncthreads();
    {
        int o = t >> 3, c4 = (t & 7) * 4;
        float4 v = make_float4(s_out[o * 33 + c4],     s_out[o * 33 + c4 + 1],
                               s_out[o * 33 + c4 + 2], s_out[o * 33 + c4 + 3]);
        *reinterpret_cast<float4*>(out_b + o * NPTS + n0 + c4) = v;
    }
}

// ---------------- launch ----------------------------------------------------
extern "C" void kernel_launch(void* const* d_in, const int* in_sizes, int n_in,
                              void* d_out, int out_size)
{
    const float* points = (const float*)d_in[0];
    const float* img    = (const float*)d_in[1];
    const float* dist   = (const float*)d_in[2];
    const int*   idx    = (const int*)  d_in[3];

    prep_kernel<<<1, 256>>>(
        (const float*)d_in[4],  (const float*)d_in[5],
        (const float*)d_in[6],  (const float*)d_in[7],
        (const float*)d_in[8],  (const float*)d_in[9],
        (const float*)d_in[10], (const float*)d_in[11],
        (const float*)d_in[12], (const float*)d_in[13],
        (const float*)d_in[14], (const float*)d_in[15]);

    cudaFuncSetAttribute(pif_main, cudaFuncAttributeMaxDynamicSharedMemorySize,
                         SMEM_BYTES);
    pif_main<<<NBLOCKS, THREADS, SMEM_BYTES>>>(points, img, dist, idx,
                                               (float*)d_out);
}